// round 1
// baseline (speedup 1.0000x reference)
#include <cuda_runtime.h>
#include <cuda_bf16.h>

// out[(half*128 + 2f), i]   = sin(coord[half][i] * inv_freq[f])
// out[(half*128 + 2f+1), i] = cos(coord[half][i] * inv_freq[f])
// half = 0 -> Y row, half = 1 -> X row. num = 262144, 64 freqs, out (256, num).

__global__ __launch_bounds__(128)
void pe_offgrid_kernel(const float* __restrict__ YX,
                       const float* __restrict__ inv_freq,
                       float* __restrict__ out,
                       int num) {
    int r = blockIdx.y;            // 0..127 : (half, freq)
    int half = r >> 6;             // 0 or 1
    int f = r & 63;                // 0..63
    float freq = __ldg(inv_freq + f);

    int i0 = (blockIdx.x * blockDim.x + threadIdx.x) << 2;  // 4 elems per thread
    if (i0 + 3 >= num && i0 >= num) return;

    const float4 c4 = *reinterpret_cast<const float4*>(YX + (size_t)half * num + i0);

    float4 s, c;
    sincosf(c4.x * freq, &s.x, &c.x);
    sincosf(c4.y * freq, &s.y, &c.y);
    sincosf(c4.z * freq, &s.z, &c.z);
    sincosf(c4.w * freq, &s.w, &c.w);

    float* base = out + ((size_t)(half * 128 + 2 * f)) * (size_t)num + i0;
    *reinterpret_cast<float4*>(base)       = s;   // sin row
    *reinterpret_cast<float4*>(base + num) = c;   // cos row
}

extern "C" void kernel_launch(void* const* d_in, const int* in_sizes, int n_in,
                              void* d_out, int out_size) {
    const float* YX       = (const float*)d_in[0];   // (2, num) fp32
    const float* inv_freq = (const float*)d_in[1];   // (64,)   fp32
    float* out            = (float*)d_out;           // (256, num) fp32

    int num = in_sizes[0] / 2;                       // 262144

    const int TPB = 128;
    int i_blocks = (num + TPB * 4 - 1) / (TPB * 4);  // 512
    dim3 grid(i_blocks, 128);                        // 128 = 2 halves * 64 freqs
    pe_offgrid_kernel<<<grid, TPB>>>(YX, inv_freq, out, num);
}